// round 3
// baseline (speedup 1.0000x reference)
#include <cuda_runtime.h>
#include <cuda_bf16.h>

// Problem constants
#define BATCH 16
#define NPTS 2048            // N == M == 2048
#define NPAIRS (NPTS / 2)    // 1024 packed target pairs
#define NUM_CLASSES 40
#define THREADS 256
#define CHUNKS 4             // 512 query points per block
#define NBLOCKS (2 * BATCH * CHUNKS)   // 128

// Deterministic scratch (no device allocation allowed)
__device__ float g_partials[NBLOCKS];
__device__ int   g_count = 0;   // self-resetting completion counter

// Packed f32x2 helpers (sm_103a FFMA2 — only reachable via PTX)
#define FMA2(acc, a, b) \
    asm("fma.rn.f32x2 %0, %1, %2, %0;" : "+l"(acc) : "l"(a), "l"(b))
#define PACK_REP(dst, s) \
    asm("mov.b64 %0, {%1, %1};" : "=l"(dst) : "f"(s))
#define UNPACK2(lo, hi, src) \
    asm("mov.b64 {%0, %1}, %2;" : "=f"(lo), "=f"(hi) : "l"(src))

// One block: one (direction, batch, chunk-of-512-query-points).
// SMEM holds the target cloud in pair-interleaved SoA:
//   sA[p] = (x_{2p}, x_{2p+1}, y_{2p}, y_{2p+1})
//   sB[p] = (z_{2p}, z_{2p+1}, w_{2p}, w_{2p+1})   w = |y|^2
// so one LDS.128 gives two ready-packed b64 f32x2 operands.
// d(x,y) = |x|^2 + (w - 2 x.y); |x|^2 hoisted out of the min,
// -2 folded into the packed query registers.
__global__ __launch_bounds__(THREADS, 1)
void chamfer_kernel(const float* __restrict__ reg,
                    const float* __restrict__ p1,
                    const float* __restrict__ pred,
                    const int*   __restrict__ target32,
                    float* __restrict__ out) {
    __shared__ float4 sA[NPAIRS];     // 16 KB
    __shared__ float4 sB[NPAIRS];     // 16 KB
    __shared__ float  sred[THREADS];
    __shared__ int    s_last;

    const int blk   = blockIdx.x;
    const int dir   = blk >> 6;
    const int rem   = blk & 63;
    const int b     = rem >> 2;
    const int chunk = rem & 3;
    const int tid   = threadIdx.x;

    const float* __restrict__ xsrc = dir ? p1 : reg;
    const float* __restrict__ ysrc = dir ? reg : p1;
    const float* xb = xsrc + (size_t)b * NPTS * 3;
    const float* yb = ysrc + (size_t)b * NPTS * 3;

    // Fill pair-interleaved SoA tile, precompute |y|^2
    for (int p = tid; p < NPAIRS; p += THREADS) {
        const float a0 = yb[6 * p + 0], a1 = yb[6 * p + 1], a2 = yb[6 * p + 2];
        const float b0 = yb[6 * p + 3], b1 = yb[6 * p + 4], b2 = yb[6 * p + 5];
        sA[p] = make_float4(a0, b0, a1, b1);
        sB[p] = make_float4(a2, b2,
                            a0 * a0 + a1 * a1 + a2 * a2,
                            b0 * b0 + b1 * b1 + b2 * b2);
    }
    __syncthreads();

    // This thread's 2 query points; pack -2*coord replicated into b64 regs
    const int q0 = chunk * 512 + tid;
    const int q1 = q0 + 256;
    const float x0 = xb[q0 * 3 + 0], y0 = xb[q0 * 3 + 1], z0 = xb[q0 * 3 + 2];
    const float x1 = xb[q1 * 3 + 0], y1 = xb[q1 * 3 + 1], z1 = xb[q1 * 3 + 2];
    const float n0 = x0 * x0 + y0 * y0 + z0 * z0;
    const float n1 = x1 * x1 + y1 * y1 + z1 * z1;

    unsigned long long X0, Y0, Z0, X1, Y1, Z1;
    PACK_REP(X0, -2.0f * x0); PACK_REP(Y0, -2.0f * y0); PACK_REP(Z0, -2.0f * z0);
    PACK_REP(X1, -2.0f * x1); PACK_REP(Y1, -2.0f * y1); PACK_REP(Z1, -2.0f * z1);

    const ulonglong2* __restrict__ pA = reinterpret_cast<const ulonglong2*>(sA);
    const ulonglong2* __restrict__ pB = reinterpret_cast<const ulonglong2*>(sB);

    // Split min accumulators (lo/hi lane) shorten the FMNMX chain
    float m0a = 3.0e38f, m0b = 3.0e38f, m1a = 3.0e38f, m1b = 3.0e38f;

    #pragma unroll 4
    for (int p = 0; p < NPAIRS; p++) {
        const ulonglong2 qa = pA[p];   // .x = xpair, .y = ypair
        const ulonglong2 qb = pB[p];   // .x = zpair, .y = wpair

        unsigned long long t0 = qb.y;  // acc = {w_j, w_j+1}
        FMA2(t0, X0, qa.x);
        FMA2(t0, Y0, qa.y);
        FMA2(t0, Z0, qb.x);
        float lo0, hi0; UNPACK2(lo0, hi0, t0);
        m0a = fminf(m0a, lo0);
        m0b = fminf(m0b, hi0);

        unsigned long long t1 = qb.y;
        FMA2(t1, X1, qa.x);
        FMA2(t1, Y1, qa.y);
        FMA2(t1, Z1, qb.x);
        float lo1, hi1; UNPACK2(lo1, hi1, t1);
        m1a = fminf(m1a, lo1);
        m1b = fminf(m1b, hi1);
    }

    float s = (n0 + fminf(m0a, m0b)) + (n1 + fminf(m1a, m1b));

    // Deterministic block tree-reduction
    sred[tid] = s;
    __syncthreads();
    #pragma unroll
    for (int off = THREADS / 2; off >= 32; off >>= 1) {
        if (tid < off) sred[tid] += sred[tid + off];
        __syncthreads();
    }
    if (tid < 32) {
        float v = sred[tid];
        #pragma unroll
        for (int off = 16; off > 0; off >>= 1)
            v += __shfl_down_sync(0xFFFFFFFFu, v, off);
        if (tid == 0) g_partials[blk] = v;
    }

    // Fused finalize: last block to finish sums partials + NLL.
    if (tid == 0) {
        __threadfence();
        const int r = atomicAdd(&g_count, 1);
        s_last = (r == NBLOCKS - 1);
    }
    __syncthreads();
    if (!s_last) return;
    __threadfence();   // acquire: make other blocks' partials visible

    // tid < NBLOCKS: reload partials (volatile), tree-reduce
    float v = 0.0f;
    if (tid < NBLOCKS) {
        volatile float* vp = g_partials;
        v = vp[tid];
    }
    sred[tid] = v;
    __syncthreads();
    #pragma unroll
    for (int off = THREADS / 2; off >= 32; off >>= 1) {
        if (tid < off) sred[tid] += sred[tid + off];
        __syncthreads();
    }
    if (tid < 32) {
        float w = sred[tid];
        #pragma unroll
        for (int off = 16; off > 0; off >>= 1)
            w += __shfl_down_sync(0xFFFFFFFFu, w, off);
        if (tid == 0) {
            const float reg_loss = w / (float)(BATCH * NPTS);

            // dtype sniff: JAX x64-disabled emits int32 despite declared int64.
            // int64 iff all odd 32-bit words of the 16 entries are zero
            // (false-positive prob with int32 targets in [0,40): 40^-8 ~ 0).
            bool is64 = true;
            #pragma unroll
            for (int i = 0; i < 8; i++)
                if (target32[2 * i + 1] != 0) is64 = false;

            float nll = 0.0f;
            #pragma unroll
            for (int i = 0; i < BATCH; i++) {
                int t = is64 ? target32[2 * i] : target32[i];
                t = (t < 0) ? 0 : (t >= NUM_CLASSES ? NUM_CLASSES - 1 : t);
                nll -= pred[i * NUM_CLASSES + t];
            }
            nll /= (float)BATCH;
            out[0] = nll + reg_loss;
            g_count = 0;   // self-reset for next graph replay
        }
    }
}

extern "C" void kernel_launch(void* const* d_in, const int* in_sizes, int n_in,
                              void* d_out, int out_size) {
    const float* reg    = (const float*)d_in[0];   // [16, 2048, 3]
    const float* p1     = (const float*)d_in[1];   // [16, 2048, 3]
    const float* pred   = (const float*)d_in[2];   // [16, 40] log-probs
    const int*   target = (const int*)d_in[3];     // [16] int32 (or int64, sniffed)
    float* out = (float*)d_out;

    chamfer_kernel<<<NBLOCKS, THREADS>>>(reg, p1, pred, target, out);
}

// round 4
// speedup vs baseline: 1.1361x; 1.1361x over previous
#include <cuda_runtime.h>
#include <cuda_bf16.h>

// Problem constants
#define BATCH 16
#define NPTS 2048            // N == M == 2048
#define NPAIRS (NPTS / 2)    // 1024 packed target pairs
#define NUM_CLASSES 40
#define THREADS 256
#define CHUNKS 8             // 256 query points per block, 1 per thread
#define NBLOCKS (2 * BATCH * CHUNKS)   // 256

// Deterministic scratch (no device allocation allowed)
__device__ float g_partials[NBLOCKS];
__device__ int   g_count = 0;   // self-resetting completion counter

// Packed f32x2 helpers (sm_103a FFMA2 — only reachable via PTX)
#define FMA2(acc, a, b) \
    asm("fma.rn.f32x2 %0, %1, %2, %0;" : "+l"(acc) : "l"(a), "l"(b))
#define PACK_REP(dst, s) \
    asm("mov.b64 %0, {%1, %1};" : "=l"(dst) : "f"(s))
#define UNPACK2(lo, hi, src) \
    asm("mov.b64 {%0, %1}, %2;" : "=f"(lo), "=f"(hi) : "l"(src))

// One block: one (direction, batch, chunk-of-256-query-points), 1 pt/thread.
// SMEM holds the target cloud pair-interleaved SoA:
//   sA[p] = (x_{2p}, x_{2p+1}, y_{2p}, y_{2p+1})
//   sB[p] = (z_{2p}, z_{2p+1}, w_{2p}, w_{2p+1})   w = |y|^2
// One LDS.128 yields two ready-packed b64 f32x2 operands (broadcast, N=1).
// d(x,y) = |x|^2 + (w - 2 x.y); |x|^2 hoisted out of the min,
// -2 folded into the packed query registers.
__global__ __launch_bounds__(THREADS, 2)
void chamfer_kernel(const float* __restrict__ reg,
                    const float* __restrict__ p1,
                    const float* __restrict__ pred,
                    const int*   __restrict__ target32,
                    float* __restrict__ out) {
    __shared__ float4 sA[NPAIRS];     // 16 KB
    __shared__ float4 sB[NPAIRS];     // 16 KB
    __shared__ float  sred[THREADS];
    __shared__ int    s_last;

    const int blk   = blockIdx.x;
    const int dir   = blk >> 7;       // 0: x=reg,y=p1 ; 1: x=p1,y=reg
    const int rem   = blk & 127;
    const int b     = rem >> 3;
    const int chunk = rem & 7;
    const int tid   = threadIdx.x;

    const float* __restrict__ xsrc = dir ? p1 : reg;
    const float* __restrict__ ysrc = dir ? reg : p1;
    const float* xb = xsrc + (size_t)b * NPTS * 3;
    const float* yb = ysrc + (size_t)b * NPTS * 3;

    // Fill pair-interleaved SoA tile, precompute |y|^2
    for (int p = tid; p < NPAIRS; p += THREADS) {
        const float a0 = yb[6 * p + 0], a1 = yb[6 * p + 1], a2 = yb[6 * p + 2];
        const float b0 = yb[6 * p + 3], b1 = yb[6 * p + 4], b2 = yb[6 * p + 5];
        sA[p] = make_float4(a0, b0, a1, b1);
        sB[p] = make_float4(a2, b2,
                            a0 * a0 + a1 * a1 + a2 * a2,
                            b0 * b0 + b1 * b1 + b2 * b2);
    }
    __syncthreads();

    // This thread's single query point; pack -2*coord replicated into b64 regs
    const int q0 = chunk * THREADS + tid;
    const float x0 = xb[q0 * 3 + 0], y0 = xb[q0 * 3 + 1], z0 = xb[q0 * 3 + 2];
    const float n0 = x0 * x0 + y0 * y0 + z0 * z0;

    unsigned long long X0, Y0, Z0;
    PACK_REP(X0, -2.0f * x0); PACK_REP(Y0, -2.0f * y0); PACK_REP(Z0, -2.0f * z0);

    const ulonglong2* __restrict__ pA = reinterpret_cast<const ulonglong2*>(sA);
    const ulonglong2* __restrict__ pB = reinterpret_cast<const ulonglong2*>(sB);

    // Split min accumulators (lo/hi lane) keep FMNMX chains parallel
    float m0a = 3.0e38f, m0b = 3.0e38f;

    #pragma unroll 8
    for (int p = 0; p < NPAIRS; p++) {
        const ulonglong2 qa = pA[p];   // .x = xpair, .y = ypair
        const ulonglong2 qb = pB[p];   // .x = zpair, .y = wpair

        unsigned long long t0 = qb.y;  // acc = {w_j, w_j+1}
        FMA2(t0, X0, qa.x);
        FMA2(t0, Y0, qa.y);
        FMA2(t0, Z0, qb.x);
        float lo0, hi0; UNPACK2(lo0, hi0, t0);
        m0a = fminf(m0a, lo0);
        m0b = fminf(m0b, hi0);
    }

    float s = n0 + fminf(m0a, m0b);

    // Deterministic block tree-reduction
    sred[tid] = s;
    __syncthreads();
    #pragma unroll
    for (int off = THREADS / 2; off >= 32; off >>= 1) {
        if (tid < off) sred[tid] += sred[tid + off];
        __syncthreads();
    }
    if (tid < 32) {
        float v = sred[tid];
        #pragma unroll
        for (int off = 16; off > 0; off >>= 1)
            v += __shfl_down_sync(0xFFFFFFFFu, v, off);
        if (tid == 0) g_partials[blk] = v;
    }

    // Fused finalize: last block to finish sums partials + NLL.
    if (tid == 0) {
        __threadfence();
        const int r = atomicAdd(&g_count, 1);
        s_last = (r == NBLOCKS - 1);
    }
    __syncthreads();
    if (!s_last) return;
    __threadfence();   // acquire: make other blocks' partials visible

    // NBLOCKS == THREADS: each thread reloads one partial (volatile)
    {
        volatile float* vp = g_partials;
        sred[tid] = vp[tid];
    }
    __syncthreads();
    #pragma unroll
    for (int off = THREADS / 2; off >= 32; off >>= 1) {
        if (tid < off) sred[tid] += sred[tid + off];
        __syncthreads();
    }
    if (tid < 32) {
        float w = sred[tid];
        #pragma unroll
        for (int off = 16; off > 0; off >>= 1)
            w += __shfl_down_sync(0xFFFFFFFFu, w, off);
        if (tid == 0) {
            const float reg_loss = w / (float)(BATCH * NPTS);

            // dtype sniff: JAX x64-disabled emits int32 despite declared int64.
            // int64 iff all odd 32-bit words of the 16 entries are zero
            // (false-positive prob with int32 targets in [0,40): 40^-8 ~ 0).
            bool is64 = true;
            #pragma unroll
            for (int i = 0; i < 8; i++)
                if (target32[2 * i + 1] != 0) is64 = false;

            float nll = 0.0f;
            #pragma unroll
            for (int i = 0; i < BATCH; i++) {
                int t = is64 ? target32[2 * i] : target32[i];
                t = (t < 0) ? 0 : (t >= NUM_CLASSES ? NUM_CLASSES - 1 : t);
                nll -= pred[i * NUM_CLASSES + t];
            }
            nll /= (float)BATCH;
            out[0] = nll + reg_loss;
            g_count = 0;   // self-reset for next graph replay
        }
    }
}

extern "C" void kernel_launch(void* const* d_in, const int* in_sizes, int n_in,
                              void* d_out, int out_size) {
    const float* reg    = (const float*)d_in[0];   // [16, 2048, 3]
    const float* p1     = (const float*)d_in[1];   // [16, 2048, 3]
    const float* pred   = (const float*)d_in[2];   // [16, 40] log-probs
    const int*   target = (const int*)d_in[3];     // [16] int32 (or int64, sniffed)
    float* out = (float*)d_out;

    chamfer_kernel<<<NBLOCKS, THREADS>>>(reg, p1, pred, target, out);
}

// round 5
// speedup vs baseline: 1.5639x; 1.3766x over previous
#include <cuda_runtime.h>
#include <cuda_bf16.h>

// Problem constants
#define BATCH 16
#define NPTS 2048              // N == M == 2048
#define NPAIRS (NPTS / 2)      // 1024 packed target pairs
#define NUM_CLASSES 40
#define THREADS 256
#define QCHUNKS 16             // 128 queries per block
#define NBLOCKS (2 * BATCH * QCHUNKS)   // 512
#define QPB 128                // queries per block
#define PAIRS_PER_QUARTER (NPAIRS / 4)  // 256

// Deterministic scratch (no device allocation allowed)
__device__ float g_partials[NBLOCKS];
__device__ int   g_count = 0;   // self-resetting completion counter

// Packed f32x2 helpers (sm_103a FFMA2 — only reachable via PTX)
#define FMA2(acc, a, b) \
    asm("fma.rn.f32x2 %0, %1, %2, %0;" : "+l"(acc) : "l"(a), "l"(b))
#define PACK_REP(dst, s) \
    asm("mov.b64 %0, {%1, %1};" : "=l"(dst) : "f"(s))
#define UNPACK2(lo, hi, src) \
    asm("mov.b64 {%0, %1}, %2;" : "=f"(lo), "=f"(hi) : "l"(src))

// One block: (direction, batch, chunk-of-128-queries).
// 256 threads: thread owns queries {q, q+64} (q = chunk*128 + tid%64) and
// scans target-quarter tid/64 (256 of 1024 pairs). Mins are combined across
// the 4 quarter-threads in SMEM, then tree-summed.
// SMEM target tile, pair-interleaved SoA:
//   sA[p] = (x_{2p}, x_{2p+1}, y_{2p}, y_{2p+1})
//   sB[p] = (z_{2p}, z_{2p+1}, w_{2p}, w_{2p+1})   w = |y|^2
// d(x,y) = |x|^2 + (w - 2 x.y); -2 folded into packed query regs.
__global__ __launch_bounds__(THREADS, 4)
void chamfer_kernel(const float* __restrict__ reg,
                    const float* __restrict__ p1,
                    const float* __restrict__ pred,
                    const int*   __restrict__ target32,
                    float* __restrict__ out) {
    __shared__ float4 sA[NPAIRS];      // 16 KB
    __shared__ float4 sB[NPAIRS];      // 16 KB
    __shared__ float  sredA[THREADS];  // per-thread min for query slot A
    __shared__ float  sredB[THREADS];  // per-thread min for query slot B
    __shared__ int    s_last;

    const int blk     = blockIdx.x;
    const int dir     = blk >> 8;        // 512 blocks: bit 8 = direction
    const int rem     = blk & 255;
    const int b       = rem >> 4;
    const int chunk   = rem & 15;
    const int tid     = threadIdx.x;
    const int j       = tid & 63;        // query lane 0..63
    const int quarter = tid >> 6;        // target quarter 0..3

    const float* __restrict__ xsrc = dir ? p1 : reg;
    const float* __restrict__ ysrc = dir ? reg : p1;
    const float* xb = xsrc + (size_t)b * NPTS * 3;
    const float* yb = ysrc + (size_t)b * NPTS * 3;

    // Fill pair-interleaved SoA tile, precompute |y|^2 (4 pairs per thread)
    for (int p = tid; p < NPAIRS; p += THREADS) {
        const float a0 = yb[6 * p + 0], a1 = yb[6 * p + 1], a2 = yb[6 * p + 2];
        const float b0 = yb[6 * p + 3], b1 = yb[6 * p + 4], b2 = yb[6 * p + 5];
        sA[p] = make_float4(a0, b0, a1, b1);
        sB[p] = make_float4(a2, b2,
                            a0 * a0 + a1 * a1 + a2 * a2,
                            b0 * b0 + b1 * b1 + b2 * b2);
    }
    __syncthreads();

    // This thread's 2 query points; pack -2*coord replicated into b64 regs
    const int q0 = chunk * QPB + j;
    const int q1 = q0 + 64;
    const float x0 = xb[q0 * 3 + 0], y0 = xb[q0 * 3 + 1], z0 = xb[q0 * 3 + 2];
    const float x1 = xb[q1 * 3 + 0], y1 = xb[q1 * 3 + 1], z1 = xb[q1 * 3 + 2];
    const float n0 = x0 * x0 + y0 * y0 + z0 * z0;
    const float n1 = x1 * x1 + y1 * y1 + z1 * z1;

    unsigned long long X0, Y0, Z0, X1, Y1, Z1;
    PACK_REP(X0, -2.0f * x0); PACK_REP(Y0, -2.0f * y0); PACK_REP(Z0, -2.0f * z0);
    PACK_REP(X1, -2.0f * x1); PACK_REP(Y1, -2.0f * y1); PACK_REP(Z1, -2.0f * z1);

    const ulonglong2* __restrict__ pA = reinterpret_cast<const ulonglong2*>(sA);
    const ulonglong2* __restrict__ pB = reinterpret_cast<const ulonglong2*>(sB);

    // Split min accumulators (lo/hi lane) keep FMNMX chains parallel
    float m0a = 3.0e38f, m0b = 3.0e38f, m1a = 3.0e38f, m1b = 3.0e38f;

    const int pbeg = quarter * PAIRS_PER_QUARTER;
    #pragma unroll 4
    for (int p = pbeg; p < pbeg + PAIRS_PER_QUARTER; p++) {
        const ulonglong2 qa = pA[p];   // .x = xpair, .y = ypair
        const ulonglong2 qb = pB[p];   // .x = zpair, .y = wpair

        unsigned long long t0 = qb.y;  // acc = {w_j, w_j+1}
        FMA2(t0, X0, qa.x);
        FMA2(t0, Y0, qa.y);
        FMA2(t0, Z0, qb.x);
        float lo0, hi0; UNPACK2(lo0, hi0, t0);
        m0a = fminf(m0a, lo0);
        m0b = fminf(m0b, hi0);

        unsigned long long t1 = qb.y;
        FMA2(t1, X1, qa.x);
        FMA2(t1, Y1, qa.y);
        FMA2(t1, Z1, qb.x);
        float lo1, hi1; UNPACK2(lo1, hi1, t1);
        m1a = fminf(m1a, lo1);
        m1b = fminf(m1b, hi1);
    }

    sredA[tid] = fminf(m0a, m0b);
    sredB[tid] = fminf(m1a, m1b);
    __syncthreads();

    // Combine quarters + add norms: only quarter-0 threads (tid < 64)
    float s = 0.0f;
    if (tid < 64) {
        const float mA = fminf(fminf(sredA[tid], sredA[tid + 64]),
                               fminf(sredA[tid + 128], sredA[tid + 192]));
        const float mB = fminf(fminf(sredB[tid], sredB[tid + 64]),
                               fminf(sredB[tid + 128], sredB[tid + 192]));
        s = (n0 + mA) + (n1 + mB);
    }
    __syncthreads();
    sredA[tid] = s;
    __syncthreads();
    if (tid < 32) {
        float v = sredA[tid] + sredA[tid + 32];
        #pragma unroll
        for (int off = 16; off > 0; off >>= 1)
            v += __shfl_down_sync(0xFFFFFFFFu, v, off);
        if (tid == 0) g_partials[blk] = v;
    }

    // Fused finalize: last block to finish sums partials + NLL.
    if (tid == 0) {
        __threadfence();
        const int r = atomicAdd(&g_count, 1);
        s_last = (r == NBLOCKS - 1);
    }
    __syncthreads();
    if (!s_last) return;
    __threadfence();   // acquire: make other blocks' partials visible

    // 512 partials, 256 threads: 2 each (volatile reload)
    {
        volatile float* vp = g_partials;
        sredA[tid] = vp[tid] + vp[tid + THREADS];
    }
    __syncthreads();
    #pragma unroll
    for (int off = THREADS / 2; off >= 32; off >>= 1) {
        if (tid < off) sredA[tid] += sredA[tid + off];
        __syncthreads();
    }
    if (tid < 32) {
        float w = sredA[tid];
        #pragma unroll
        for (int off = 16; off > 0; off >>= 1)
            w += __shfl_down_sync(0xFFFFFFFFu, w, off);
        if (tid == 0) {
            const float reg_loss = w / (float)(BATCH * NPTS);

            // dtype sniff: JAX x64-disabled emits int32 despite declared int64.
            // int64 iff all odd 32-bit words of the 16 entries are zero
            // (false-positive prob with int32 targets in [0,40): 40^-8 ~ 0).
            bool is64 = true;
            #pragma unroll
            for (int i = 0; i < 8; i++)
                if (target32[2 * i + 1] != 0) is64 = false;

            float nll = 0.0f;
            #pragma unroll
            for (int i = 0; i < BATCH; i++) {
                int t = is64 ? target32[2 * i] : target32[i];
                t = (t < 0) ? 0 : (t >= NUM_CLASSES ? NUM_CLASSES - 1 : t);
                nll -= pred[i * NUM_CLASSES + t];
            }
            nll /= (float)BATCH;
            out[0] = nll + reg_loss;
            g_count = 0;   // self-reset for next graph replay
        }
    }
}

extern "C" void kernel_launch(void* const* d_in, const int* in_sizes, int n_in,
                              void* d_out, int out_size) {
    const float* reg    = (const float*)d_in[0];   // [16, 2048, 3]
    const float* p1     = (const float*)d_in[1];   // [16, 2048, 3]
    const float* pred   = (const float*)d_in[2];   // [16, 40] log-probs
    const int*   target = (const int*)d_in[3];     // [16] int32 (or int64, sniffed)
    float* out = (float*)d_out;

    chamfer_kernel<<<NBLOCKS, THREADS>>>(reg, p1, pred, target, out);
}

// round 6
// speedup vs baseline: 1.7528x; 1.1208x over previous
#include <cuda_runtime.h>
#include <cuda_bf16.h>

// Problem constants
#define BATCH 16
#define NPTS 2048              // N == M == 2048
#define NPAIRS (NPTS / 2)      // 1024 packed target pairs
#define NUM_CLASSES 40
#define THREADS 256
#define QCHUNKS 16             // 128 queries per block
#define NBLOCKS (2 * BATCH * QCHUNKS)   // 512
#define QPB 128                // queries per block (32 lanes x 4 per thread)
#define NGROUPS 8              // target-groups per block
#define PAIRS_PER_GROUP (NPAIRS / NGROUPS)  // 128

// Deterministic scratch (no device allocation allowed)
__device__ float g_partials[NBLOCKS];
__device__ int   g_count = 0;   // self-resetting completion counter

// Packed f32x2 helpers (sm_103a FFMA2 — only reachable via PTX)
#define FMA2(acc, a, b) \
    asm("fma.rn.f32x2 %0, %1, %2, %0;" : "+l"(acc) : "l"(a), "l"(b))
#define PACK_REP(dst, s) \
    asm("mov.b64 %0, {%1, %1};" : "=l"(dst) : "f"(s))
#define UNPACK2(lo, hi, src) \
    asm("mov.b64 {%0, %1}, %2;" : "=f"(lo), "=f"(hi) : "l"(src))

// One block: (direction, batch, chunk-of-128-queries).
// 256 threads = 32 query-lanes x 8 target-groups. Thread (lane, grp) owns
// queries q = chunk*128 + lane + s*32 (s=0..3) and scans target-group grp
// (128 of 1024 pairs). Four independent FFMA2 chains per LDS pair.
// SMEM target tile, pair-interleaved SoA:
//   sA[p] = (x_{2p}, x_{2p+1}, y_{2p}, y_{2p+1})
//   sB[p] = (z_{2p}, z_{2p+1}, w_{2p}, w_{2p+1})   w = |y|^2
// d(x,y) = |x|^2 + (w - 2 x.y); -2 folded into packed query regs.
__global__ __launch_bounds__(THREADS, 3)
void chamfer_kernel(const float* __restrict__ reg,
                    const float* __restrict__ p1,
                    const float* __restrict__ pred,
                    const int*   __restrict__ target32,
                    float* __restrict__ out) {
    __shared__ float4 sA[NPAIRS];          // 16 KB
    __shared__ float4 sB[NPAIRS];          // 16 KB
    __shared__ float  smin[4][THREADS];    // 4 KB per-thread mins per query slot
    __shared__ float  sred[64];
    __shared__ int    s_last;

    const int blk   = blockIdx.x;
    const int dir   = blk >> 8;          // 512 blocks: bit 8 = direction
    const int rem   = blk & 255;
    const int b     = rem >> 4;
    const int chunk = rem & 15;
    const int tid   = threadIdx.x;
    const int lane  = tid & 31;          // query lane 0..31
    const int grp   = tid >> 5;          // target group 0..7

    const float* __restrict__ xsrc = dir ? p1 : reg;
    const float* __restrict__ ysrc = dir ? reg : p1;
    const float* xb = xsrc + (size_t)b * NPTS * 3;
    const float* yb = ysrc + (size_t)b * NPTS * 3;

    // Fill pair-interleaved SoA tile, precompute |y|^2 (4 pairs per thread)
    for (int p = tid; p < NPAIRS; p += THREADS) {
        const float a0 = yb[6 * p + 0], a1 = yb[6 * p + 1], a2 = yb[6 * p + 2];
        const float b0 = yb[6 * p + 3], b1 = yb[6 * p + 4], b2 = yb[6 * p + 5];
        sA[p] = make_float4(a0, b0, a1, b1);
        sB[p] = make_float4(a2, b2,
                            a0 * a0 + a1 * a1 + a2 * a2,
                            b0 * b0 + b1 * b1 + b2 * b2);
    }
    __syncthreads();

    // 4 query points per thread (same 4 for all 8 groups of a lane)
    const int qbase = chunk * QPB + lane;
    float n[4];
    unsigned long long X[4], Y[4], Z[4];
    #pragma unroll
    for (int s = 0; s < 4; s++) {
        const int q = qbase + 32 * s;
        const float xq = xb[q * 3 + 0], yq = xb[q * 3 + 1], zq = xb[q * 3 + 2];
        n[s] = xq * xq + yq * yq + zq * zq;
        PACK_REP(X[s], -2.0f * xq);
        PACK_REP(Y[s], -2.0f * yq);
        PACK_REP(Z[s], -2.0f * zq);
    }

    const ulonglong2* __restrict__ pA = reinterpret_cast<const ulonglong2*>(sA);
    const ulonglong2* __restrict__ pB = reinterpret_cast<const ulonglong2*>(sB);

    // Split min accumulators (lo/hi lane) per query slot
    float ma[4] = {3.0e38f, 3.0e38f, 3.0e38f, 3.0e38f};
    float mb[4] = {3.0e38f, 3.0e38f, 3.0e38f, 3.0e38f};

    const int pbeg = grp * PAIRS_PER_GROUP;
    #pragma unroll 4
    for (int p = pbeg; p < pbeg + PAIRS_PER_GROUP; p++) {
        const ulonglong2 qa = pA[p];   // .x = xpair, .y = ypair
        const ulonglong2 qb = pB[p];   // .x = zpair, .y = wpair
        #pragma unroll
        for (int s = 0; s < 4; s++) {
            unsigned long long t = qb.y;    // acc = {w_j, w_j+1}
            FMA2(t, X[s], qa.x);
            FMA2(t, Y[s], qa.y);
            FMA2(t, Z[s], qb.x);
            float lo, hi; UNPACK2(lo, hi, t);
            ma[s] = fminf(ma[s], lo);
            mb[s] = fminf(mb[s], hi);
        }
    }

    #pragma unroll
    for (int s = 0; s < 4; s++)
        smin[s][tid] = fminf(ma[s], mb[s]);
    __syncthreads();

    // Combine the 8 groups per (lane, slot): warp 0 does it (owns same queries)
    float v = 0.0f;
    if (tid < 32) {
        float acc = 0.0f;
        #pragma unroll
        for (int s = 0; s < 4; s++) {
            float m = smin[s][lane];
            #pragma unroll
            for (int g = 1; g < NGROUPS; g++)
                m = fminf(m, smin[s][32 * g + lane]);
            acc += n[s] + m;
        }
        v = acc;
        #pragma unroll
        for (int off = 16; off > 0; off >>= 1)
            v += __shfl_down_sync(0xFFFFFFFFu, v, off);
        if (tid == 0) g_partials[blk] = v;
    }

    // Fused finalize: last block to finish sums partials + NLL.
    if (tid == 0) {
        __threadfence();
        const int r = atomicAdd(&g_count, 1);
        s_last = (r == NBLOCKS - 1);
    }
    __syncthreads();
    if (!s_last) return;
    __threadfence();   // acquire: make other blocks' partials visible

    // 512 partials, 256 threads: 2 each (volatile reload), warp-level finish
    float w;
    {
        volatile float* vp = g_partials;
        w = vp[tid] + vp[tid + THREADS];
    }
    {
        #pragma unroll
        for (int off = 16; off > 0; off >>= 1)
            w += __shfl_down_sync(0xFFFFFFFFu, w, off);
        if ((tid & 31) == 0) sred[tid >> 5] = w;
    }
    __syncthreads();
    if (tid == 0) {
        float tot = 0.0f;
        #pragma unroll
        for (int i = 0; i < THREADS / 32; i++) tot += sred[i];
        const float reg_loss = tot / (float)(BATCH * NPTS);

        // dtype sniff: JAX x64-disabled emits int32 despite declared int64.
        // int64 iff all odd 32-bit words of the 16 entries are zero
        // (false-positive prob with int32 targets in [0,40): 40^-8 ~ 0).
        bool is64 = true;
        #pragma unroll
        for (int i = 0; i < 8; i++)
            if (target32[2 * i + 1] != 0) is64 = false;

        float nll = 0.0f;
        #pragma unroll
        for (int i = 0; i < BATCH; i++) {
            int t = is64 ? target32[2 * i] : target32[i];
            t = (t < 0) ? 0 : (t >= NUM_CLASSES ? NUM_CLASSES - 1 : t);
            nll -= pred[i * NUM_CLASSES + t];
        }
        nll /= (float)BATCH;
        out[0] = nll + reg_loss;
        g_count = 0;   // self-reset for next graph replay
    }
}

extern "C" void kernel_launch(void* const* d_in, const int* in_sizes, int n_in,
                              void* d_out, int out_size) {
    const float* reg    = (const float*)d_in[0];   // [16, 2048, 3]
    const float* p1     = (const float*)d_in[1];   // [16, 2048, 3]
    const float* pred   = (const float*)d_in[2];   // [16, 40] log-probs
    const int*   target = (const int*)d_in[3];     // [16] int32 (or int64, sniffed)
    float* out = (float*)d_out;

    chamfer_kernel<<<NBLOCKS, THREADS>>>(reg, p1, pred, target, out);
}